// round 1
// baseline (speedup 1.0000x reference)
#include <cuda_runtime.h>
#include <math.h>

// Problem constants
#define B_  4
#define L_  2048
#define C_  2048
#define NH_ 32
#define HD_ 64
#define K_  16
#define NC_ 128           // L/K chunks
#define LR_ 1.0f
#define EPS_ 1e-6f

// Scratch (device globals; no allocation allowed)
__device__ float g_XC[(size_t)B_ * NH_ * L_ * HD_];   // [b][h][l][d]
__device__ float g_XB[(size_t)B_ * NH_ * L_ * HD_];
__device__ float g_XA[(size_t)B_ * NH_ * L_ * HD_];
__device__ float g_XCW[(size_t)B_ * L_ * C_];         // [b][l][h*64+d]
__device__ float g_coeff[(size_t)B_ * NH_ * L_];      // [b][h][l]

// ---------------------------------------------------------------------------
// SGEMM body: C = A(MxK) @ B(KxN), M=8192 rows of A, K=N=2048.
// 128x128 block tile, BK=8, 256 threads, 8x8 microtile.
// MODE 0: plain row-major store to Cout[m*2048 + n]
// MODE 1: head-split scatter: Cout[((b*32+h)*2048 + l)*64 + d]
// ---------------------------------------------------------------------------
template <int MODE>
__device__ __forceinline__ void sgemm_body(const float* __restrict__ A,
                                           const float* __restrict__ Bw,
                                           float* __restrict__ Cout)
{
    const int Kdim = 2048, N = 2048;
    __shared__ float As[8][132];   // padded: conflict-free transposed stores
    __shared__ float Bs[8][128];

    int tid = threadIdx.x;
    int bm = blockIdx.y, bn = blockIdx.x;

    int arow = tid >> 1;            // 0..127
    int acol = (tid & 1) * 4;       // 0 or 4
    int brow = tid >> 5;            // 0..7
    int bcol = (tid & 31) * 4;      // 0..124

    const float* Aptr = A + (size_t)(bm * 128 + arow) * Kdim + acol;
    const float* Bptr = Bw + (size_t)brow * N + bn * 128 + bcol;

    int ty = tid >> 4, tx = tid & 15;
    float c[8][8];
    #pragma unroll
    for (int i = 0; i < 8; ++i)
        #pragma unroll
        for (int j = 0; j < 8; ++j) c[i][j] = 0.f;

    for (int k0 = 0; k0 < Kdim; k0 += 8) {
        float4 av = *(const float4*)(Aptr); Aptr += 8;
        float4 bv = *(const float4*)(Bptr); Bptr += (size_t)8 * N;
        As[acol + 0][arow] = av.x;
        As[acol + 1][arow] = av.y;
        As[acol + 2][arow] = av.z;
        As[acol + 3][arow] = av.w;
        *(float4*)&Bs[brow][bcol] = bv;
        __syncthreads();

        #pragma unroll
        for (int k = 0; k < 8; ++k) {
            float4 a0 = *(const float4*)&As[k][ty * 8];
            float4 a1 = *(const float4*)&As[k][ty * 8 + 4];
            float4 b0 = *(const float4*)&Bs[k][tx * 8];
            float4 b1 = *(const float4*)&Bs[k][tx * 8 + 4];
            float ar[8] = {a0.x, a0.y, a0.z, a0.w, a1.x, a1.y, a1.z, a1.w};
            float br[8] = {b0.x, b0.y, b0.z, b0.w, b1.x, b1.y, b1.z, b1.w};
            #pragma unroll
            for (int i = 0; i < 8; ++i)
                #pragma unroll
                for (int j = 0; j < 8; ++j)
                    c[i][j] = fmaf(ar[i], br[j], c[i][j]);
        }
        __syncthreads();
    }

    // Store
    #pragma unroll
    for (int i = 0; i < 8; ++i) {
        int m = bm * 128 + ty * 8 + i;
        int nbase = bn * 128 + tx * 8;
        float4 v0 = make_float4(c[i][0], c[i][1], c[i][2], c[i][3]);
        float4 v1 = make_float4(c[i][4], c[i][5], c[i][6], c[i][7]);
        if (MODE == 0) {
            float* dst = Cout + (size_t)m * N + nbase;
            *(float4*)dst = v0;
            *(float4*)(dst + 4) = v1;
        } else {
            int b = m >> 11, l = m & 2047;
            int h = nbase >> 6, dbase = nbase & 63;
            float* dst = Cout + ((size_t)(b * NH_ + h) * L_ + l) * HD_ + dbase;
            *(float4*)dst = v0;
            *(float4*)(dst + 4) = v1;
        }
    }
}

__global__ __launch_bounds__(256) void proj_kernel(const float* __restrict__ hs,
                                                   const float* __restrict__ Wq,
                                                   const float* __restrict__ Wk,
                                                   const float* __restrict__ Wv)
{
    int z = blockIdx.z;
    const float* Bw = (z == 0) ? Wq : ((z == 1) ? Wk : Wv);
    float* Cout = (z == 0) ? g_XC : ((z == 1) ? g_XB : g_XA);
    sgemm_body<1>(hs, Bw, Cout);
}

__global__ __launch_bounds__(256) void out_kernel(const float* __restrict__ Wo,
                                                  float* __restrict__ out)
{
    sgemm_body<0>(g_XCW, Wo, out);
}

// ---------------------------------------------------------------------------
// ilr / coeff kernel: one block per (b,l) row.
// coeff[b][h][l] = sigmoid(hs[b,l,:] @ ilr_w[:,h] + ilr_b[h]) * LR / (HD*(l%K+1))
// ---------------------------------------------------------------------------
__global__ __launch_bounds__(128) void ilr_kernel(const float* __restrict__ hs,
                                                  const float* __restrict__ ilr_w,
                                                  const float* __restrict__ ilr_b)
{
    int m = blockIdx.x;                 // b*L + l
    __shared__ float row[2048];
    __shared__ float part[128];
    int tid = threadIdx.x;
    const float* src = hs + (size_t)m * 2048;
    for (int i = tid; i < 2048; i += 128) row[i] = src[i];
    __syncthreads();

    int hh = tid & 31;
    int p = tid >> 5;                   // warp id 0..3
    float acc = 0.f;
    int kbeg = p * 512, kend = kbeg + 512;
    for (int k = kbeg; k < kend; ++k)
        acc = fmaf(row[k], ilr_w[(size_t)k * 32 + hh], acc);
    part[tid] = acc;
    __syncthreads();

    if (tid < 32) {
        float s = part[tid] + part[tid + 32] + part[tid + 64] + part[tid + 96]
                + ilr_b[tid];
        float sig = 1.f / (1.f + expf(-s));
        int b = m >> 11, l = m & 2047;
        g_coeff[((size_t)(b * NH_ + tid)) * L_ + l] =
            sig * LR_ / ((float)HD_ * (float)((l & 15) + 1));
    }
}

// ---------------------------------------------------------------------------
// Scan kernel: one block (1024 threads) per (b,h). Thread (r,d): r=tid/64 in
// [0,16), d=tid%64. W1 (64x64) + b1 live in SMEM across 128 sequential chunks.
// ---------------------------------------------------------------------------
#define PAD 65

__device__ __forceinline__ void reduce2(float& a, float& b, float* red, int tid)
{
    #pragma unroll
    for (int off = 16; off; off >>= 1) {
        a += __shfl_xor_sync(0xffffffffu, a, off);
        b += __shfl_xor_sync(0xffffffffu, b, off);
    }
    int warp = tid >> 5;
    __syncthreads();                    // previous consumers of red done
    if ((tid & 31) == 0) { red[warp * 2] = a; red[warp * 2 + 1] = b; }
    __syncthreads();
    int rr = tid >> 6;
    a = red[rr * 4 + 0] + red[rr * 4 + 2];
    b = red[rr * 4 + 1] + red[rr * 4 + 3];
}

__global__ __launch_bounds__(1024) void scan_kernel(const float* __restrict__ W1g,
                                                    const float* __restrict__ b1g,
                                                    const float* __restrict__ lnwg,
                                                    const float* __restrict__ lnbg)
{
    __shared__ float W1s[64 * 64];
    __shared__ float xbs[16 * PAD];
    __shared__ float xcs[16 * PAD];
    __shared__ float grads[16 * PAD];
    __shared__ float attns[16 * 16];
    __shared__ float b1s[64];
    __shared__ float cos_[16];
    __shared__ float red[64];

    int bh = blockIdx.x;                // b*NH + h
    int h = bh & 31;
    int b = bh >> 5;
    int tid = threadIdx.x;
    int r = tid >> 6;                   // 0..15
    int d = tid & 63;                   // 0..63

    for (int i = tid; i < 4096; i += 1024) W1s[i] = W1g[(size_t)h * 4096 + i];
    if (tid < 64) b1s[tid] = b1g[(size_t)h * 64 + tid];
    float lnw = lnwg[(size_t)h * 64 + d];
    float lnb = lnbg[(size_t)h * 64 + d];

    const float* XCp = g_XC + (size_t)bh * (L_ * HD_);
    const float* XBp = g_XB + (size_t)bh * (L_ * HD_);
    const float* XAp = g_XA + (size_t)bh * (L_ * HD_);
    const float* cop = g_coeff + (size_t)bh * L_;

    __syncthreads();

    for (int c = 0; c < NC_; ++c) {
        int base = c * (K_ * HD_) + tid;   // tid == r*64+d
        float xb_e = XBp[base];
        float xc_e = XCp[base];
        float xa_e = XAp[base];
        xbs[r * PAD + d] = xb_e;
        xcs[r * PAD + d] = xc_e;
        if (tid < 16) cos_[tid] = cop[c * 16 + tid];
        __syncthreads();

        // Z1 = xb @ W1 + b1
        float z1 = b1s[d];
        #pragma unroll
        for (int k = 0; k < 64; ++k)
            z1 = fmaf(xbs[r * PAD + k], W1s[k * 64 + d], z1);

        // ln_fused_l2_bwd
        float s1 = z1, s2 = z1 * z1;
        reduce2(s1, s2, red, tid);
        float mu = s1 * (1.f / 64.f);
        float var = s2 * (1.f / 64.f) - mu * mu;
        float rstd = rsqrtf(var + EPS_);
        float xhat = (z1 - mu) * rstd;
        float y = fmaf(lnw, xhat, lnb);
        float g = (y - (xa_e - xb_e)) * lnw;
        float sg = g, sgx = g * xhat;
        reduce2(sg, sgx, red, tid);
        float grad = (64.f * g - sg - xhat * sgx) * (rstd * (1.f / 64.f));
        grads[r * PAD + d] = grad;
        __syncthreads();

        // Attn1 = tril(xc @ xb^T) : 256 threads
        if (tid < 256) {
            int rr = tid >> 4, j = tid & 15;
            float a = 0.f;
            if (j <= rr) {
                #pragma unroll
                for (int dd = 0; dd < 64; ++dd)
                    a = fmaf(xcs[rr * PAD + dd], xbs[j * PAD + dd], a);
            }
            attns[rr * 16 + j] = a;
        }
        __syncthreads();

        // Z1_bar = xc@W1 - co*(Attn1@grad + cumsum(grad)) + b1
        float acc = b1s[d];
        #pragma unroll
        for (int k = 0; k < 64; ++k)
            acc = fmaf(xcs[r * PAD + k], W1s[k * 64 + d], acc);
        float s_attn = 0.f, s_cum = 0.f;
        #pragma unroll
        for (int j = 0; j < 16; ++j) {
            float gj = grads[j * PAD + d];
            s_attn = fmaf(attns[r * 16 + j], gj, s_attn);
            if (j <= r) s_cum += gj;
        }
        float co = cos_[r];
        float z1b = acc - co * (s_attn + s_cum);
        float b1new = 0.f;
        if (r == 15) b1new = b1s[d] - co * s_cum;   // co == cos_[15]; s_cum == total

        // ln_fwd + residual, store to XCW[b][l][h*64+d]
        float t1 = z1b, t2 = z1b * z1b;
        reduce2(t1, t2, red, tid);
        float mu2 = t1 * (1.f / 64.f);
        float rstd2 = rsqrtf(t2 * (1.f / 64.f) - mu2 * mu2 + EPS_);
        float outv = xc_e + fmaf(lnw, (z1b - mu2) * rstd2, lnb);
        int l = c * 16 + r;
        g_XCW[((size_t)(b * L_ + l)) * C_ + h * 64 + d] = outv;

        __syncthreads();   // all reads of b1s/W1s complete

        if (r == 15) b1s[d] = b1new;

        // W1 -= co15 * xb^T @ grad  (each thread: 4 k's)
        {
            int kk = tid >> 6;          // 0..15
            float c15 = cos_[15];
            #pragma unroll
            for (int s = 0; s < 4; ++s) {
                int k = kk + s * 16;
                float a = 0.f;
                #pragma unroll
                for (int rr = 0; rr < 16; ++rr)
                    a = fmaf(xbs[rr * PAD + k], grads[rr * PAD + d], a);
                W1s[k * 64 + d] -= c15 * a;
            }
        }
        __syncthreads();
    }
}

// ---------------------------------------------------------------------------
extern "C" void kernel_launch(void* const* d_in, const int* in_sizes, int n_in,
                              void* d_out, int out_size)
{
    const float* hs    = (const float*)d_in[0];
    const float* Wq    = (const float*)d_in[1];
    const float* Wk    = (const float*)d_in[2];
    const float* Wv    = (const float*)d_in[3];
    const float* Wo    = (const float*)d_in[4];
    const float* ilr_w = (const float*)d_in[5];
    const float* ilr_b = (const float*)d_in[6];
    const float* lnw   = (const float*)d_in[7];
    const float* lnb   = (const float*)d_in[8];
    const float* W1    = (const float*)d_in[9];
    const float* b1    = (const float*)d_in[10];
    float* out = (float*)d_out;

    dim3 gproj(C_ / 128, (B_ * L_) / 128, 3);
    proj_kernel<<<gproj, 256>>>(hs, Wq, Wk, Wv);

    ilr_kernel<<<B_ * L_, 128>>>(hs, ilr_w, ilr_b);

    scan_kernel<<<B_ * NH_, 1024>>>(W1, b1, lnw, lnb);

    dim3 gout(C_ / 128, (B_ * L_) / 128, 1);
    out_kernel<<<gout, 256>>>(Wo, out);
}

// round 4
// speedup vs baseline: 2.0486x; 2.0486x over previous
#include <cuda_runtime.h>
#include <cuda_bf16.h>
#include <math.h>
#include <stdint.h>

// Problem constants
#define B_  4
#define L_  2048
#define C_  2048
#define NH_ 32
#define HD_ 64
#define K_  16
#define NC_ 128
#define EPS_ 1e-6f
#define M_  8192          // B_*L_

// ---------------------------------------------------------------------------
// Device-global scratch
// ---------------------------------------------------------------------------
__device__ __nv_bfloat16 g_Ah[(size_t)M_ * C_];        // hs hi
__device__ __nv_bfloat16 g_Al[(size_t)M_ * C_];        // hs lo
__device__ __nv_bfloat16 g_Wh[(size_t)4 * C_ * C_];    // Wq,Wk,Wv,Wo transposed [N][K] hi
__device__ __nv_bfloat16 g_Wl[(size_t)4 * C_ * C_];    // lo
__device__ __nv_bfloat16 g_XCWh[(size_t)M_ * C_];      // scan output hi
__device__ __nv_bfloat16 g_XCWl[(size_t)M_ * C_];      // scan output lo
__device__ float g_XC[(size_t)B_ * NH_ * L_ * HD_];    // [b][h][l][d]
__device__ float g_XB[(size_t)B_ * NH_ * L_ * HD_];
__device__ float g_XA[(size_t)B_ * NH_ * L_ * HD_];
__device__ float g_coeff[(size_t)B_ * NH_ * L_];

// ---------------------------------------------------------------------------
// Helpers
// ---------------------------------------------------------------------------
__device__ __forceinline__ uint32_t smem_u32(const void* p) {
    uint32_t a;
    asm("{ .reg .u64 t; cvta.to.shared.u64 t, %1; cvt.u32.u64 %0, t; }"
        : "=r"(a) : "l"(p));
    return a;
}

#define CP_ASYNC16(smaddr, gptr) \
    asm volatile("cp.async.cg.shared.global [%0], [%1], 16;" \
                 :: "r"(smaddr), "l"(gptr))
#define CP_COMMIT() asm volatile("cp.async.commit_group;")
#define CP_WAIT0()  asm volatile("cp.async.wait_group 0;")
#define CP_WAIT1()  asm volatile("cp.async.wait_group 1;")

#define LDSM_X4(r0, r1, r2, r3, addr) \
    asm volatile("ldmatrix.sync.aligned.m8n8.x4.shared.b16 {%0,%1,%2,%3}, [%4];" \
                 : "=r"(r0), "=r"(r1), "=r"(r2), "=r"(r3) : "r"(addr))

__device__ __forceinline__ void mma_bf16(float* c, const uint32_t* a,
                                         uint32_t b0, uint32_t b1) {
    asm volatile(
        "mma.sync.aligned.m16n8k16.row.col.f32.bf16.bf16.f32 "
        "{%0,%1,%2,%3}, {%4,%5,%6,%7}, {%8,%9}, {%0,%1,%2,%3};"
        : "+f"(c[0]), "+f"(c[1]), "+f"(c[2]), "+f"(c[3])
        : "r"(a[0]), "r"(a[1]), "r"(a[2]), "r"(a[3]), "r"(b0), "r"(b1));
}

// ---------------------------------------------------------------------------
// Prep kernels
// ---------------------------------------------------------------------------
__global__ __launch_bounds__(256) void convhs_kernel(const float* __restrict__ hs)
{
    size_t i = ((size_t)blockIdx.x * 256 + threadIdx.x) * 4;
    float4 v = *(const float4*)(hs + i);
    __nv_bfloat16 h0 = __float2bfloat16(v.x), h1 = __float2bfloat16(v.y);
    __nv_bfloat16 h2 = __float2bfloat16(v.z), h3 = __float2bfloat16(v.w);
    g_Ah[i] = h0; g_Ah[i+1] = h1; g_Ah[i+2] = h2; g_Ah[i+3] = h3;
    g_Al[i]   = __float2bfloat16(v.x - __bfloat162float(h0));
    g_Al[i+1] = __float2bfloat16(v.y - __bfloat162float(h1));
    g_Al[i+2] = __float2bfloat16(v.z - __bfloat162float(h2));
    g_Al[i+3] = __float2bfloat16(v.w - __bfloat162float(h3));
}

__global__ __launch_bounds__(256) void wtrans_kernel(
    const float* __restrict__ Wq, const float* __restrict__ Wk,
    const float* __restrict__ Wv, const float* __restrict__ Wo)
{
    __shared__ float t[32][33];
    int z = blockIdx.z;
    const float* W = (z == 0) ? Wq : (z == 1) ? Wk : (z == 2) ? Wv : Wo;
    __nv_bfloat16* Oh = g_Wh + (size_t)z * (C_ * C_);
    __nv_bfloat16* Ol = g_Wl + (size_t)z * (C_ * C_);
    int n0 = blockIdx.x * 32, k0 = blockIdx.y * 32;
    int tx = threadIdx.x & 31, ty = threadIdx.x >> 5;
    #pragma unroll
    for (int i = 0; i < 4; ++i)
        t[ty + 8 * i][tx] = W[(size_t)(k0 + ty + 8 * i) * C_ + n0 + tx];
    __syncthreads();
    #pragma unroll
    for (int i = 0; i < 4; ++i) {
        float v = t[tx][ty + 8 * i];
        __nv_bfloat16 hv = __float2bfloat16(v);
        size_t o = (size_t)(n0 + ty + 8 * i) * C_ + k0 + tx;
        Oh[o] = hv;
        Ol[o] = __float2bfloat16(v - __bfloat162float(hv));
    }
}

// ---------------------------------------------------------------------------
// mma.sync GEMM: D[M,N] = A[M,K] @ B^T[N,K], 3-pass bf16 hi/lo split.
// 128x128 block tile, BK=32, 256 threads (8 warps, warp tile 64x32).
// SMEM: padded rows of 80B (conflict-free ldmatrix), 4 matrices/stage,
// double-buffered cp.async pipeline.
// MODE 1: A=g_Ah/Al, B=Wq/Wk/Wv by z, scatter out to g_XC/XB/XA
// MODE 0: A=g_XCWh/l, B=Wo, plain store to Cout
// ---------------------------------------------------------------------------
#define ROWB 80
#define MATB (128 * ROWB)          // 10240
#define STGB (4 * MATB)            // 40960
#define GEMM_SMEM (2 * STGB)       // 81920

__device__ __forceinline__ void load_stage(uint32_t sb,
    const __nv_bfloat16* __restrict__ Ah, const __nv_bfloat16* __restrict__ Al,
    const __nv_bfloat16* __restrict__ Bh, const __nv_bfloat16* __restrict__ Bl,
    int am0, int bn0, int kc, int tid)
{
    #pragma unroll
    for (int it = 0; it < 2; ++it) {
        int u = tid + it * 256;
        int row = u >> 2, ch = u & 3;
        int gcol = kc * 32 + ch * 8;
        uint32_t so = (uint32_t)(row * ROWB + ch * 16);
        size_t ga = (size_t)(am0 + row) * C_ + gcol;
        size_t gb = (size_t)(bn0 + row) * C_ + gcol;
        CP_ASYNC16(sb + so,            Ah + ga);
        CP_ASYNC16(sb + so + MATB,     Al + ga);
        CP_ASYNC16(sb + so + 2 * MATB, Bh + gb);
        CP_ASYNC16(sb + so + 3 * MATB, Bl + gb);
    }
}

template <int MODE>
__global__ __launch_bounds__(256) void gemm_mma(float* __restrict__ Cout)
{
    extern __shared__ char sm[];
    uint32_t sbase = smem_u32(sm);
    int tid = threadIdx.x, wid = tid >> 5, lane = tid & 31;
    int bn = blockIdx.x, bm = blockIdx.y;
    int wm = wid & 1, wn = wid >> 1;     // warp 64x32 tile: 2 x 4 warps

    const __nv_bfloat16 *Ah, *Al, *Bh, *Bl;
    float* outP;
    if (MODE == 1) {
        int z = blockIdx.z;
        Ah = g_Ah; Al = g_Al;
        Bh = g_Wh + (size_t)z * (C_ * C_);
        Bl = g_Wl + (size_t)z * (C_ * C_);
        outP = (z == 0) ? g_XC : (z == 1) ? g_XB : g_XA;
    } else {
        Ah = g_XCWh; Al = g_XCWl;
        Bh = g_Wh + (size_t)3 * (C_ * C_);
        Bl = g_Wl + (size_t)3 * (C_ * C_);
        outP = Cout;
    }
    int am0 = bm * 128, bn0 = bn * 128;

    float acc[4][4][4];
    #pragma unroll
    for (int i = 0; i < 4; ++i)
        #pragma unroll
        for (int j = 0; j < 4; ++j)
            #pragma unroll
            for (int q = 0; q < 4; ++q) acc[i][j][q] = 0.f;

    // Per-lane ldmatrix address components
    int a_row = wm * 64 + (lane & 15);        // + mt*16
    int a_cb  = (lane >> 4) * 16;             // byte col within k16 block
    int g = lane >> 3, l8 = lane & 7;
    int b_row = wn * 32 + (g >> 1) * 8 + l8;  // + p*16
    int b_cb  = (g & 1) * 16;                 // byte col

    load_stage(sbase, Ah, Al, Bh, Bl, am0, bn0, 0, tid);
    CP_COMMIT();

    for (int c = 0; c < 64; ++c) {
        int st = c & 1;
        if (c + 1 < 64) {
            load_stage(sbase + (st ^ 1) * STGB, Ah, Al, Bh, Bl, am0, bn0, c + 1, tid);
            CP_COMMIT();
            CP_WAIT1();
        } else {
            CP_WAIT0();
        }
        __syncthreads();

        uint32_t S = sbase + st * STGB;
        #pragma unroll
        for (int k16 = 0; k16 < 2; ++k16) {
            uint32_t kb = (uint32_t)(k16 * 32);
            // B fragments: 4 n-tiles x 2 regs, hi and lo
            uint32_t bh[8], bl[8];
            {
                uint32_t ad0 = S + 2 * MATB + (uint32_t)((b_row) * ROWB) + kb + b_cb;
                uint32_t ad1 = ad0 + 16 * ROWB;
                LDSM_X4(bh[0], bh[1], bh[2], bh[3], ad0);
                LDSM_X4(bh[4], bh[5], bh[6], bh[7], ad1);
                uint32_t bd0 = ad0 + MATB, bd1 = ad1 + MATB;
                LDSM_X4(bl[0], bl[1], bl[2], bl[3], bd0);
                LDSM_X4(bl[4], bl[5], bl[6], bl[7], bd1);
            }
            #pragma unroll
            for (int mt = 0; mt < 4; ++mt) {
                uint32_t ah[4], al[4];
                uint32_t aad = S + (uint32_t)((a_row + mt * 16) * ROWB) + kb + a_cb;
                LDSM_X4(ah[0], ah[1], ah[2], ah[3], aad);
                LDSM_X4(al[0], al[1], al[2], al[3], aad + MATB);
                #pragma unroll
                for (int nt = 0; nt < 4; ++nt) {
                    mma_bf16(acc[mt][nt], ah, bh[nt * 2], bh[nt * 2 + 1]);
                    mma_bf16(acc[mt][nt], ah, bl[nt * 2], bl[nt * 2 + 1]);
                    mma_bf16(acc[mt][nt], al, bh[nt * 2], bh[nt * 2 + 1]);
                }
            }
        }
        __syncthreads();
    }

    // Epilogue: c-fragment rows = lane>>2 (+8), cols = 2*(lane&3)+{0,1}
    #pragma unroll
    for (int mt = 0; mt < 4; ++mt) {
        #pragma unroll
        for (int nt = 0; nt < 4; ++nt) {
            int m = am0 + wm * 64 + mt * 16 + (lane >> 2);
            int n = bn0 + wn * 32 + nt * 8 + 2 * (lane & 3);
            float2 v0 = make_float2(acc[mt][nt][0], acc[mt][nt][1]);
            float2 v1 = make_float2(acc[mt][nt][2], acc[mt][nt][3]);
            if (MODE == 0) {
                *(float2*)(outP + (size_t)m * C_ + n) = v0;
                *(float2*)(outP + (size_t)(m + 8) * C_ + n) = v1;
            } else {
                int h = n >> 6, d = n & 63;
                int b = m >> 11, l = m & 2047;
                float* dst = outP + ((size_t)(b * NH_ + h) * L_ + l) * HD_ + d;
                *(float2*)dst = v0;
                *(float2*)(dst + 8 * HD_) = v1;
            }
        }
    }
}

// ---------------------------------------------------------------------------
// ilr / coeff
// ---------------------------------------------------------------------------
__global__ __launch_bounds__(512) void ilr_kernel(const float* __restrict__ hs,
                                                  const float* __restrict__ ilr_w,
                                                  const float* __restrict__ ilr_b)
{
    int h = threadIdx.x & 31, mr = threadIdx.x >> 5;
    int m = blockIdx.x * 16 + mr;
    const float* row = hs + (size_t)m * C_;
    float acc = 0.f;
    for (int k = 0; k < C_; k += 4) {
        float4 x = *(const float4*)(row + k);
        acc = fmaf(x.x, ilr_w[(size_t)(k + 0) * 32 + h], acc);
        acc = fmaf(x.y, ilr_w[(size_t)(k + 1) * 32 + h], acc);
        acc = fmaf(x.z, ilr_w[(size_t)(k + 2) * 32 + h], acc);
        acc = fmaf(x.w, ilr_w[(size_t)(k + 3) * 32 + h], acc);
    }
    acc += ilr_b[h];
    float sig = 1.f / (1.f + expf(-acc));
    int b = m >> 11, l = m & 2047;
    g_coeff[((size_t)(b * NH_ + h)) * L_ + l] =
        sig * (1.0f / (float)HD_) / (float)((l & 15) + 1);
}

// ---------------------------------------------------------------------------
// Scan kernel + bf16 hi/lo epilogue into g_XCWh/l
// ---------------------------------------------------------------------------
#define PAD 65

__device__ __forceinline__ void reduce2(float& a, float& b, float* red, int tid)
{
    #pragma unroll
    for (int off = 16; off; off >>= 1) {
        a += __shfl_xor_sync(0xffffffffu, a, off);
        b += __shfl_xor_sync(0xffffffffu, b, off);
    }
    int warp = tid >> 5;
    __syncthreads();
    if ((tid & 31) == 0) { red[warp * 2] = a; red[warp * 2 + 1] = b; }
    __syncthreads();
    int rr = tid >> 6;
    a = red[rr * 4 + 0] + red[rr * 4 + 2];
    b = red[rr * 4 + 1] + red[rr * 4 + 3];
}

__global__ __launch_bounds__(1024) void scan_kernel(const float* __restrict__ W1g,
                                                    const float* __restrict__ b1g,
                                                    const float* __restrict__ lnwg,
                                                    const float* __restrict__ lnbg)
{
    __shared__ float W1s[64 * 64];
    __shared__ float xbs[16 * PAD];
    __shared__ float xcs[16 * PAD];
    __shared__ float grads[16 * PAD];
    __shared__ float attns[16 * 16];
    __shared__ float b1s[64];
    __shared__ float cos_[16];
    __shared__ float red[64];

    int bh = blockIdx.x;
    int h = bh & 31;
    int b = bh >> 5;
    int tid = threadIdx.x;
    int r = tid >> 6;
    int d = tid & 63;

    for (int i = tid; i < 4096; i += 1024) W1s[i] = W1g[(size_t)h * 4096 + i];
    if (tid < 64) b1s[tid] = b1g[(size_t)h * 64 + tid];
    float lnw = lnwg[(size_t)h * 64 + d];
    float lnb = lnbg[(size_t)h * 64 + d];

    const float* XCp = g_XC + (size_t)bh * (L_ * HD_);
    const float* XBp = g_XB + (size_t)bh * (L_ * HD_);
    const float* XAp = g_XA + (size_t)bh * (L_ * HD_);
    const float* cop = g_coeff + (size_t)bh * L_;

    __syncthreads();

    for (int c = 0; c < NC_; ++c) {
        int base = c * (K_ * HD_) + tid;
        float xb_e = XBp[base];
        float xc_e = XCp[base];
        float xa_e = XAp[base];
        xbs[r * PAD + d] = xb_e;
        xcs[r * PAD + d] = xc_e;
        if (tid < 16) cos_[tid] = cop[c * 16 + tid];
        __syncthreads();

        float z1 = b1s[d];
        #pragma unroll
        for (int k = 0; k < 64; ++k)
            z1 = fmaf(xbs[r * PAD + k], W1s[k * 64 + d], z1);

        float s1 = z1, s2 = z1 * z1;
        reduce2(s1, s2, red, tid);
        float mu = s1 * (1.f / 64.f);
        float var = s2 * (1.f / 64.f) - mu * mu;
        float rstd = rsqrtf(var + EPS_);
        float xhat = (z1 - mu) * rstd;
        float y = fmaf(lnw, xhat, lnb);
        float g = (y - (xa_e - xb_e)) * lnw;
        float sg = g, sgx = g * xhat;
        reduce2(sg, sgx, red, tid);
        float grad = (64.f * g - sg - xhat * sgx) * (rstd * (1.f / 64.f));
        grads[r * PAD + d] = grad;
        __syncthreads();

        if (tid < 256) {
            int rr = tid >> 4, j = tid & 15;
            float a = 0.f;
            if (j <= rr) {
                #pragma unroll
                for (int dd = 0; dd < 64; ++dd)
                    a = fmaf(xcs[rr * PAD + dd], xbs[j * PAD + dd], a);
            }
            attns[rr * 16 + j] = a;
        }
        __syncthreads();

        float acc = b1s[d];
        #pragma unroll
        for (int k = 0; k < 64; ++k)
            acc = fmaf(xcs[r * PAD + k], W1s[k * 64 + d], acc);
        float s_attn = 0.f, s_cum = 0.f;
        #pragma unroll
        for (int j = 0; j < 16; ++j) {
            float gj = grads[j * PAD + d];
            s_attn = fmaf(attns[r * 16 + j], gj, s_attn);
            if (j <= r) s_cum += gj;
        }
        float co = cos_[r];
        float z1b = acc - co * (s_attn + s_cum);
        float b1new = 0.f;
        if (r == 15) b1new = b1s[d] - co * s_cum;

        float t1 = z1b, t2 = z1b * z1b;
        reduce2(t1, t2, red, tid);
        float mu2 = t1 * (1.f / 64.f);
        float rstd2 = rsqrtf(t2 * (1.f / 64.f) - mu2 * mu2 + EPS_);
        float outv = xc_e + fmaf(lnw, (z1b - mu2) * rstd2, lnb);
        int l = c * 16 + r;
        size_t oidx = ((size_t)(b * L_ + l)) * C_ + h * 64 + d;
        __nv_bfloat16 hv = __float2bfloat16(outv);
        g_XCWh[oidx] = hv;
        g_XCWl[oidx] = __float2bfloat16(outv - __bfloat162float(hv));

        __syncthreads();

        if (r == 15) b1s[d] = b1new;

        {
            int kk = tid >> 6;
            float c15 = cos_[15];
            #pragma unroll
            for (int s = 0; s < 4; ++s) {
                int k = kk + s * 16;
                float a = 0.f;
                #pragma unroll
                for (int rr = 0; rr < 16; ++rr)
                    a = fmaf(xbs[rr * PAD + k], grads[rr * PAD + d], a);
                W1s[k * 64 + d] -= c15 * a;
            }
        }
        __syncthreads();
    }
}

// ---------------------------------------------------------------------------
extern "C" void kernel_launch(void* const* d_in, const int* in_sizes, int n_in,
                              void* d_out, int out_size)
{
    const float* hs    = (const float*)d_in[0];
    const float* Wq    = (const float*)d_in[1];
    const float* Wk    = (const float*)d_in[2];
    const float* Wv    = (const float*)d_in[3];
    const float* Wo    = (const float*)d_in[4];
    const float* ilr_w = (const float*)d_in[5];
    const float* ilr_b = (const float*)d_in[6];
    const float* lnw   = (const float*)d_in[7];
    const float* lnb   = (const float*)d_in[8];
    const float* W1    = (const float*)d_in[9];
    const float* b1    = (const float*)d_in[10];
    float* out = (float*)d_out;

    cudaFuncSetAttribute(gemm_mma<1>, cudaFuncAttributeMaxDynamicSharedMemorySize, GEMM_SMEM);
    cudaFuncSetAttribute(gemm_mma<0>, cudaFuncAttributeMaxDynamicSharedMemorySize, GEMM_SMEM);

    convhs_kernel<<<(M_ * C_) / (256 * 4), 256>>>(hs);
    wtrans_kernel<<<dim3(C_ / 32, C_ / 32, 4), 256>>>(Wq, Wk, Wv, Wo);
    ilr_kernel<<<M_ / 16, 512>>>(hs, ilr_w, ilr_b);

    gemm_mma<1><<<dim3(C_ / 128, M_ / 128, 3), 256, GEMM_SMEM>>>(nullptr);

    scan_kernel<<<B_ * NH_, 1024>>>(W1, b1, lnw, lnb);

    gemm_mma<0><<<dim3(C_ / 128, M_ / 128, 1), 256, GEMM_SMEM>>>(out);
}